// round 6
// baseline (speedup 1.0000x reference)
#include <cuda_runtime.h>
#include <cuda_bf16.h>
#include <math_constants.h>

#define H_OUT 228
#define W_OUT 304
#define S_RAS 304
#define N_V   8192
#define M_F   2048
#define FAR_V 100.0f
#define EPS_V 1e-7f
#define FCHUNK 512

// scratch (no allocations allowed)
__device__ float  g_vx[N_V];
__device__ float  g_vy[N_V];
__device__ float  g_vz[N_V];
__device__ float4 g_face[M_F * 3];

// ---------------------------------------------------------------------------
// 1) vertex transform: depthmap -> cam -> R,t -> project -> NDC
// ---------------------------------------------------------------------------
__global__ void transform_kernel(const float* __restrict__ verts,
                                 const float* __restrict__ Km,
                                 const float* __restrict__ Rm,
                                 const float* __restrict__ tm,
                                 int n)
{
    int i = blockIdx.x * blockDim.x + threadIdx.x;
    if (i >= n) return;

    float k0 = Km[0], k1 = Km[1], k2 = Km[2];
    float k3 = Km[3], k4 = Km[4], k5 = Km[5];
    float k6 = Km[6], k7 = Km[7], k8 = Km[8];

    // adjugate inverse of K
    float c00 = k4 * k8 - k5 * k7;
    float c01 = k5 * k6 - k3 * k8;
    float c02 = k3 * k7 - k4 * k6;
    float det = k0 * c00 + k1 * c01 + k2 * c02;
    float id  = 1.0f / det;
    float i00 = c00 * id, i01 = (k2 * k7 - k1 * k8) * id, i02 = (k1 * k5 - k2 * k4) * id;
    float i10 = c01 * id, i11 = (k0 * k8 - k2 * k6) * id, i12 = (k2 * k3 - k0 * k5) * id;
    float i20 = c02 * id, i21 = (k1 * k6 - k0 * k7) * id, i22 = (k0 * k4 - k1 * k3) * id;

    float u = verts[3 * i + 0];
    float v = verts[3 * i + 1];
    float d = verts[3 * i + 2];

    float p0 = u * (float)W_OUT;
    float p1 = v * (float)H_OUT;

    float cx = (i00 * p0 + i01 * p1 + i02) * d;
    float cy = (i10 * p0 + i11 * p1 + i12) * d;
    float cz = (i20 * p0 + i21 * p1 + i22) * d;

    float qx = Rm[0] * cx + Rm[1] * cy + Rm[2] * cz + tm[0];
    float qy = Rm[3] * cx + Rm[4] * cy + Rm[5] * cz + tm[1];
    float qz = Rm[6] * cx + Rm[7] * cy + Rm[8] * cz + tm[2];

    float zd  = qz + EPS_V;
    float ppx = qx / zd;
    float ppy = qy / zd;

    float s0 = k0 * ppx + k1 * ppy + k2;
    float s1 = k3 * ppx + k4 * ppy + k5;

    float u2 = fminf(fmaxf(s0 / (float)W_OUT, 0.0f), 1.0f);
    float v2 = fminf(fmaxf(s1 / (float)H_OUT, 0.0f), 1.0f);

    // ndc: (u*W)/S*2 - 1, (v*H)/S*2 - 1  (same op order as reference)
    g_vx[i] = (u2 * (float)W_OUT) / (float)S_RAS * 2.0f - 1.0f;
    g_vy[i] = (v2 * (float)H_OUT) / (float)S_RAS * 2.0f - 1.0f;
    g_vz[i] = qz;
}

// ---------------------------------------------------------------------------
// 2) per-face edge coefficients
//    fa = (y1-y2, x2-x1, x2, y2)
//    fb = (y2-y0, x0-x2, 1/safe, 0)
//    fc = (1/z0, 1/z1, 1/z2, 0)
//    degenerate (|denom|<=1e-10): x2,y2 -> NaN  =>  inside always false
// ---------------------------------------------------------------------------
__global__ void face_kernel(const int* __restrict__ faces, int m)
{
    int f = blockIdx.x * blockDim.x + threadIdx.x;
    if (f >= m) return;

    int i0 = faces[3 * f + 0];
    int i1 = faces[3 * f + 1];
    int i2 = faces[3 * f + 2];

    float x0 = g_vx[i0], y0 = g_vy[i0], z0 = g_vz[i0];
    float x1 = g_vx[i1], y1 = g_vy[i1], z1 = g_vz[i1];
    float x2 = g_vx[i2], y2 = g_vy[i2], z2 = g_vz[i2];

    float y12 = y1 - y2;
    float x21 = x2 - x1;
    float y20 = y2 - y0;
    float x02 = x0 - x2;

    float denom = y12 * (x0 - x2) + x21 * (y0 - y2);
    bool  ok    = fabsf(denom) > 1e-10f;
    float inv_safe = 1.0f / (ok ? denom : 1.0f);

    float nanf_ = __int_as_float(0x7fc00000);
    float fx2 = ok ? x2 : nanf_;
    float fy2 = ok ? y2 : nanf_;

    g_face[3 * f + 0] = make_float4(y12, x21, fx2, fy2);
    g_face[3 * f + 1] = make_float4(y20, x02, inv_safe, 0.0f);
    g_face[3 * f + 2] = make_float4(1.0f / z0, 1.0f / z1, 1.0f / z2, 0.0f);
}

// ---------------------------------------------------------------------------
// 3) rasterize: each thread owns 2 adjacent output pixels (same row).
//    depth = min over inside faces of 1/inv_z  ==  1 / max(inv_z)  (monotone)
// ---------------------------------------------------------------------------
__global__ void __launch_bounds__(256, 2) raster_kernel(float* __restrict__ out)
{
    __shared__ float4 s[FCHUNK * 3];

    const int tid   = blockIdx.x * blockDim.x + threadIdx.x;
    const int r     = tid / (W_OUT / 2);
    const int cpair = tid % (W_OUT / 2);
    const bool valid = (r < H_OUT);
    const int c0 = 2 * cpair;

    // output row r maps to raster grid row (S-1-r); p[i] = (2i+1-S)/S
    const float py  = (float)(S_RAS - 1 - 2 * r) / (float)S_RAS;
    const float px0 = (float)(2 * c0 + 1 - S_RAS) / (float)S_RAS;
    const float px1 = (float)(2 * c0 + 3 - S_RAS) / (float)S_RAS;

    float m0 = -1.0f, m1 = -1.0f;     // max inv_z over inside faces
    float sil0 = 0.0f, sil1 = 0.0f;

    for (int base = 0; base < M_F; base += FCHUNK) {
        __syncthreads();
        for (int j = threadIdx.x; j < FCHUNK * 3; j += blockDim.x)
            s[j] = g_face[base * 3 + j];
        __syncthreads();

        #pragma unroll 4
        for (int f = 0; f < FCHUNK; f++) {
            float4 fa = s[3 * f + 0];
            float4 fb = s[3 * f + 1];
            float4 fc = s[3 * f + 2];

            float dy = py - fa.w;
            float t0 = fa.y * dy;          // (x2-x1)*(py-y2)
            float t1 = fb.y * dy;          // (x0-x2)*(py-y2)
            float dx0 = px0 - fa.z;
            float dx1 = px1 - fa.z;

            // pixel a
            float w0a = fmaf(fa.x, dx0, t0) * fb.z;
            float w1a = fmaf(fb.x, dx0, t1) * fb.z;
            float w2a = 1.0f - w0a - w1a;
            bool  ia  = (w0a >= 0.0f) && (w1a >= 0.0f) && (w2a >= 0.0f);
            float iza = fmaf(w0a, fc.x, fmaf(w1a, fc.y, w2a * fc.z));
            if (ia) { m0 = fmaxf(m0, iza); sil0 = 1.0f; }

            // pixel b
            float w0b = fmaf(fa.x, dx1, t0) * fb.z;
            float w1b = fmaf(fb.x, dx1, t1) * fb.z;
            float w2b = 1.0f - w0b - w1b;
            bool  ib  = (w0b >= 0.0f) && (w1b >= 0.0f) && (w2b >= 0.0f);
            float izb = fmaf(w0b, fc.x, fmaf(w1b, fc.y, w2b * fc.z));
            if (ib) { m1 = fmaxf(m1, izb); sil1 = 1.0f; }
        }
    }

    if (valid) {
        float d0 = (m0 > 0.0f) ? fminf(FAR_V, 1.0f / m0) : FAR_V;
        float d1 = (m1 > 0.0f) ? fminf(FAR_V, 1.0f / m1) : FAR_V;
        out[r * W_OUT + c0]                     = d0;
        out[r * W_OUT + c0 + 1]                 = d1;
        out[H_OUT * W_OUT + r * W_OUT + c0]     = sil0;
        out[H_OUT * W_OUT + r * W_OUT + c0 + 1] = sil1;
    }
}

// ---------------------------------------------------------------------------
extern "C" void kernel_launch(void* const* d_in, const int* in_sizes, int n_in,
                              void* d_out, int out_size)
{
    const float* verts = (const float*)d_in[0];   // [1,8192,3] f32
    const int*   faces = (const int*)  d_in[1];   // [1,2048,3] i32
    const float* Km    = (const float*)d_in[2];   // [1,3,3]
    const float* Rm    = (const float*)d_in[3];   // [1,3,3]
    const float* tm    = (const float*)d_in[4];   // [1,3,1]
    float* out = (float*)d_out;

    transform_kernel<<<(N_V + 255) / 256, 256>>>(verts, Km, Rm, tm, N_V);
    face_kernel<<<(M_F + 255) / 256, 256>>>(faces, M_F);

    const int n_threads = H_OUT * (W_OUT / 2);    // 34656
    const int n_blocks  = (n_threads + 255) / 256; // 136
    raster_kernel<<<n_blocks, 256>>>(out);
}

// round 7
// speedup vs baseline: 1.0026x; 1.0026x over previous
#include <cuda_runtime.h>
#include <cuda_bf16.h>
#include <math_constants.h>

#define H_OUT 228
#define W_OUT 304
#define S_RAS 304
#define N_V   8192
#define M_F   2048
#define FAR_V 100.0f
#define EPS_V 1e-7f
#define FCHUNK 512

// scratch (no allocations allowed)
__device__ float  g_vx[N_V];
__device__ float  g_vy[N_V];
__device__ float  g_vz[N_V];
__device__ float4 g_face[M_F * 3];

// ---------------------------------------------------------------------------
// 1) vertex transform: depthmap -> cam -> R,t -> project -> NDC
// ---------------------------------------------------------------------------
__global__ void transform_kernel(const float* __restrict__ verts,
                                 const float* __restrict__ Km,
                                 const float* __restrict__ Rm,
                                 const float* __restrict__ tm,
                                 int n)
{
    int i = blockIdx.x * blockDim.x + threadIdx.x;
    if (i >= n) return;

    float k0 = Km[0], k1 = Km[1], k2 = Km[2];
    float k3 = Km[3], k4 = Km[4], k5 = Km[5];
    float k6 = Km[6], k7 = Km[7], k8 = Km[8];

    // adjugate inverse of K
    float c00 = k4 * k8 - k5 * k7;
    float c01 = k5 * k6 - k3 * k8;
    float c02 = k3 * k7 - k4 * k6;
    float det = k0 * c00 + k1 * c01 + k2 * c02;
    float id  = 1.0f / det;
    float i00 = c00 * id, i01 = (k2 * k7 - k1 * k8) * id, i02 = (k1 * k5 - k2 * k4) * id;
    float i10 = c01 * id, i11 = (k0 * k8 - k2 * k6) * id, i12 = (k2 * k3 - k0 * k5) * id;
    float i20 = c02 * id, i21 = (k1 * k6 - k0 * k7) * id, i22 = (k0 * k4 - k1 * k3) * id;

    float u = verts[3 * i + 0];
    float v = verts[3 * i + 1];
    float d = verts[3 * i + 2];

    float p0 = u * (float)W_OUT;
    float p1 = v * (float)H_OUT;

    float cx = (i00 * p0 + i01 * p1 + i02) * d;
    float cy = (i10 * p0 + i11 * p1 + i12) * d;
    float cz = (i20 * p0 + i21 * p1 + i22) * d;

    float qx = Rm[0] * cx + Rm[1] * cy + Rm[2] * cz + tm[0];
    float qy = Rm[3] * cx + Rm[4] * cy + Rm[5] * cz + tm[1];
    float qz = Rm[6] * cx + Rm[7] * cy + Rm[8] * cz + tm[2];

    float zd  = qz + EPS_V;
    float ppx = qx / zd;
    float ppy = qy / zd;

    float s0 = k0 * ppx + k1 * ppy + k2;
    float s1 = k3 * ppx + k4 * ppy + k5;

    float u2 = fminf(fmaxf(s0 / (float)W_OUT, 0.0f), 1.0f);
    float v2 = fminf(fmaxf(s1 / (float)H_OUT, 0.0f), 1.0f);

    // ndc: (u*W)/S*2 - 1, (v*H)/S*2 - 1  (same op order as reference)
    g_vx[i] = (u2 * (float)W_OUT) / (float)S_RAS * 2.0f - 1.0f;
    g_vy[i] = (v2 * (float)H_OUT) / (float)S_RAS * 2.0f - 1.0f;
    g_vz[i] = qz;
}

// ---------------------------------------------------------------------------
// 2) per-face edge coefficients
//    fa = (y1-y2, x2-x1, x2, y2)
//    fb = (y2-y0, x0-x2, 1/safe, 0)
//    fc = (1/z0, 1/z1, 1/z2, 0)
//    degenerate (|denom|<=1e-10): x2,y2 -> NaN  =>  inside always false
// ---------------------------------------------------------------------------
__global__ void face_kernel(const int* __restrict__ faces, int m)
{
    int f = blockIdx.x * blockDim.x + threadIdx.x;
    if (f >= m) return;

    int i0 = faces[3 * f + 0];
    int i1 = faces[3 * f + 1];
    int i2 = faces[3 * f + 2];

    float x0 = g_vx[i0], y0 = g_vy[i0], z0 = g_vz[i0];
    float x1 = g_vx[i1], y1 = g_vy[i1], z1 = g_vz[i1];
    float x2 = g_vx[i2], y2 = g_vy[i2], z2 = g_vz[i2];

    float y12 = y1 - y2;
    float x21 = x2 - x1;
    float y20 = y2 - y0;
    float x02 = x0 - x2;

    float denom = y12 * (x0 - x2) + x21 * (y0 - y2);
    bool  ok    = fabsf(denom) > 1e-10f;
    float inv_safe = 1.0f / (ok ? denom : 1.0f);

    float nanf_ = __int_as_float(0x7fc00000);
    float fx2 = ok ? x2 : nanf_;
    float fy2 = ok ? y2 : nanf_;

    g_face[3 * f + 0] = make_float4(y12, x21, fx2, fy2);
    g_face[3 * f + 1] = make_float4(y20, x02, inv_safe, 0.0f);
    g_face[3 * f + 2] = make_float4(1.0f / z0, 1.0f / z1, 1.0f / z2, 0.0f);
}

// ---------------------------------------------------------------------------
// 3) rasterize: each thread owns 2 adjacent output pixels (same row).
//    depth = min over inside faces of 1/inv_z  ==  1 / max(inv_z)  (monotone)
// ---------------------------------------------------------------------------
__global__ void __launch_bounds__(256, 2) raster_kernel(float* __restrict__ out)
{
    __shared__ float4 s[FCHUNK * 3];

    const int tid   = blockIdx.x * blockDim.x + threadIdx.x;
    const int r     = tid / (W_OUT / 2);
    const int cpair = tid % (W_OUT / 2);
    const bool valid = (r < H_OUT);
    const int c0 = 2 * cpair;

    // output row r maps to raster grid row (S-1-r); p[i] = (2i+1-S)/S
    const float py  = (float)(S_RAS - 1 - 2 * r) / (float)S_RAS;
    const float px0 = (float)(2 * c0 + 1 - S_RAS) / (float)S_RAS;
    const float px1 = (float)(2 * c0 + 3 - S_RAS) / (float)S_RAS;

    float m0 = -1.0f, m1 = -1.0f;     // max inv_z over inside faces
    float sil0 = 0.0f, sil1 = 0.0f;

    for (int base = 0; base < M_F; base += FCHUNK) {
        __syncthreads();
        for (int j = threadIdx.x; j < FCHUNK * 3; j += blockDim.x)
            s[j] = g_face[base * 3 + j];
        __syncthreads();

        #pragma unroll 4
        for (int f = 0; f < FCHUNK; f++) {
            float4 fa = s[3 * f + 0];
            float4 fb = s[3 * f + 1];
            float4 fc = s[3 * f + 2];

            float dy = py - fa.w;
            float t0 = fa.y * dy;          // (x2-x1)*(py-y2)
            float t1 = fb.y * dy;          // (x0-x2)*(py-y2)
            float dx0 = px0 - fa.z;
            float dx1 = px1 - fa.z;

            // pixel a
            float w0a = fmaf(fa.x, dx0, t0) * fb.z;
            float w1a = fmaf(fb.x, dx0, t1) * fb.z;
            float w2a = 1.0f - w0a - w1a;
            bool  ia  = (w0a >= 0.0f) && (w1a >= 0.0f) && (w2a >= 0.0f);
            float iza = fmaf(w0a, fc.x, fmaf(w1a, fc.y, w2a * fc.z));
            if (ia) { m0 = fmaxf(m0, iza); sil0 = 1.0f; }

            // pixel b
            float w0b = fmaf(fa.x, dx1, t0) * fb.z;
            float w1b = fmaf(fb.x, dx1, t1) * fb.z;
            float w2b = 1.0f - w0b - w1b;
            bool  ib  = (w0b >= 0.0f) && (w1b >= 0.0f) && (w2b >= 0.0f);
            float izb = fmaf(w0b, fc.x, fmaf(w1b, fc.y, w2b * fc.z));
            if (ib) { m1 = fmaxf(m1, izb); sil1 = 1.0f; }
        }
    }

    if (valid) {
        float d0 = (m0 > 0.0f) ? fminf(FAR_V, 1.0f / m0) : FAR_V;
        float d1 = (m1 > 0.0f) ? fminf(FAR_V, 1.0f / m1) : FAR_V;
        out[r * W_OUT + c0]                     = d0;
        out[r * W_OUT + c0 + 1]                 = d1;
        out[H_OUT * W_OUT + r * W_OUT + c0]     = sil0;
        out[H_OUT * W_OUT + r * W_OUT + c0 + 1] = sil1;
    }
}

// ---------------------------------------------------------------------------
extern "C" void kernel_launch(void* const* d_in, const int* in_sizes, int n_in,
                              void* d_out, int out_size)
{
    const float* verts = (const float*)d_in[0];   // [1,8192,3] f32
    const int*   faces = (const int*)  d_in[1];   // [1,2048,3] i32
    const float* Km    = (const float*)d_in[2];   // [1,3,3]
    const float* Rm    = (const float*)d_in[3];   // [1,3,3]
    const float* tm    = (const float*)d_in[4];   // [1,3,1]
    float* out = (float*)d_out;

    transform_kernel<<<(N_V + 255) / 256, 256>>>(verts, Km, Rm, tm, N_V);
    face_kernel<<<(M_F + 255) / 256, 256>>>(faces, M_F);

    const int n_threads = H_OUT * (W_OUT / 2);    // 34656
    const int n_blocks  = (n_threads + 255) / 256; // 136
    raster_kernel<<<n_blocks, 256>>>(out);
}

// round 8
// speedup vs baseline: 2.0800x; 2.0746x over previous
#include <cuda_runtime.h>
#include <cuda_bf16.h>

#define H_OUT 228
#define W_OUT 304
#define S_RAS 304
#define N_V   8192
#define M_F   2048
#define NSEG  4
#define MSEG  (M_F / NSEG)       // 512
#define TILE_W 64
#define TILE_H 16
#define TILES_X 5                 // ceil(304/64)
#define TILES_Y 15                // ceil(228/16)
#define NPIX  (H_OUT * W_OUT)     // 69312
#define FAR_V 100.0f
#define EPS_V 1e-7f
#define CULL_EPS 1e-4f

// scratch (no allocations allowed)
__device__ float4 g_fa[M_F];              // (a0, b0, x2, y2)
__device__ float4 g_fb[M_F];              // (a1, b1, r0-r2, r1-r2)
__device__ float  g_r2[M_F];              // 1/z2
__device__ float4 g_bb[M_F];              // (xmin, xmax, ymin, ymax) ; NaN if degenerate
__device__ float  g_pm[NSEG * NPIX];      // per-segment max inv_z

// ---------------------------------------------------------------------------
// 1) fused vertex transform + face setup (each face transforms its 3 verts)
// ---------------------------------------------------------------------------
__global__ void prep_kernel(const float* __restrict__ verts,
                            const int*   __restrict__ faces,
                            const float* __restrict__ Km,
                            const float* __restrict__ Rm,
                            const float* __restrict__ tm)
{
    int f = blockIdx.x * blockDim.x + threadIdx.x;
    if (f >= M_F) return;

    float k0 = Km[0], k1 = Km[1], k2 = Km[2];
    float k3 = Km[3], k4 = Km[4], k5 = Km[5];
    float k6 = Km[6], k7 = Km[7], k8 = Km[8];

    // adjugate inverse of K
    float c00 = k4 * k8 - k5 * k7;
    float c01 = k5 * k6 - k3 * k8;
    float c02 = k3 * k7 - k4 * k6;
    float det = k0 * c00 + k1 * c01 + k2 * c02;
    float id  = 1.0f / det;
    float i00 = c00 * id, i01 = (k2 * k7 - k1 * k8) * id, i02 = (k1 * k5 - k2 * k4) * id;
    float i10 = c01 * id, i11 = (k0 * k8 - k2 * k6) * id, i12 = (k2 * k3 - k0 * k5) * id;
    float i20 = c02 * id, i21 = (k1 * k6 - k0 * k7) * id, i22 = (k0 * k4 - k1 * k3) * id;

    float X[3], Y[3], Z[3];
    #pragma unroll
    for (int v = 0; v < 3; v++) {
        int   idx = faces[3 * f + v];
        float u  = verts[3 * idx + 0];
        float vv = verts[3 * idx + 1];
        float d  = verts[3 * idx + 2];

        float p0 = u  * (float)W_OUT;
        float p1 = vv * (float)H_OUT;

        float cx = (i00 * p0 + i01 * p1 + i02) * d;
        float cy = (i10 * p0 + i11 * p1 + i12) * d;
        float cz = (i20 * p0 + i21 * p1 + i22) * d;

        float qx = Rm[0] * cx + Rm[1] * cy + Rm[2] * cz + tm[0];
        float qy = Rm[3] * cx + Rm[4] * cy + Rm[5] * cz + tm[1];
        float qz = Rm[6] * cx + Rm[7] * cy + Rm[8] * cz + tm[2];

        float zd  = qz + EPS_V;
        float ppx = qx / zd;
        float ppy = qy / zd;

        float s0 = k0 * ppx + k1 * ppy + k2;
        float s1 = k3 * ppx + k4 * ppy + k5;

        float u2 = fminf(fmaxf(s0 / (float)W_OUT, 0.0f), 1.0f);
        float v2 = fminf(fmaxf(s1 / (float)H_OUT, 0.0f), 1.0f);

        X[v] = (u2 * (float)W_OUT) / (float)S_RAS * 2.0f - 1.0f;
        Y[v] = (v2 * (float)H_OUT) / (float)S_RAS * 2.0f - 1.0f;
        Z[v] = qz;
    }

    float y12 = Y[1] - Y[2];
    float x21 = X[2] - X[1];
    float y20 = Y[2] - Y[0];
    float x02 = X[0] - X[2];

    float denom = y12 * (X[0] - X[2]) + x21 * (Y[0] - Y[2]);
    bool  ok    = fabsf(denom) > 1e-10f;
    float inv   = 1.0f / (ok ? denom : 1.0f);

    float a0 = y12 * inv, b0 = x21 * inv;
    float a1 = y20 * inv, b1 = x02 * inv;
    float r0 = 1.0f / Z[0], r1 = 1.0f / Z[1], r2 = 1.0f / Z[2];

    g_fa[f] = make_float4(a0, b0, X[2], Y[2]);
    g_fb[f] = make_float4(a1, b1, r0 - r2, r1 - r2);
    g_r2[f] = r2;

    float xmn = fminf(X[0], fminf(X[1], X[2]));
    float xmx = fmaxf(X[0], fmaxf(X[1], X[2]));
    float ymn = fminf(Y[0], fminf(Y[1], Y[2]));
    float ymx = fmaxf(Y[0], fmaxf(Y[1], Y[2]));
    float nanv = __int_as_float(0x7fc00000);
    g_bb[f] = ok ? make_float4(xmn, xmx, ymn, ymx)
                 : make_float4(nanv, nanv, nanv, nanv);
}

// ---------------------------------------------------------------------------
// 2) tiled raster: block = (tileX, tileY, face-segment).
//    Cull faces vs tile (bbox + conservative edge bounds), compact to smem,
//    then brute-force the survivors over 64x16 pixels (4 px/thread).
// ---------------------------------------------------------------------------
__global__ void __launch_bounds__(256) raster_kernel()
{
    __shared__ float4 sA[MSEG];
    __shared__ float4 sB[MSEG];
    __shared__ float  sR[MSEG];
    __shared__ int    s_cnt;

    const int tX = blockIdx.x, tY = blockIdx.y, seg = blockIdx.z;
    const int t  = threadIdx.x;
    if (t == 0) s_cnt = 0;
    __syncthreads();

    // tile pixel-center bounds in ndc (py decreases with row index)
    const int c0t = tX * TILE_W, r0t = tY * TILE_H;
    const float x_lo = (2.0f * c0t + 1.0f - S_RAS) / (float)S_RAS;
    const float x_hi = (2.0f * (c0t + TILE_W - 1) + 1.0f - S_RAS) / (float)S_RAS;
    const float y_hi = (float)(S_RAS - 1 - 2 * r0t) / (float)S_RAS;
    const float y_lo = (float)(S_RAS - 1 - 2 * (r0t + TILE_H - 1)) / (float)S_RAS;
    const float ctx = 0.5f * (x_lo + x_hi), cty = 0.5f * (y_lo + y_hi);
    const float hx  = 0.5f * (x_hi - x_lo), hy  = 0.5f * (y_hi - y_lo);

    // cull + compact (512 faces, 2 per thread)
    #pragma unroll
    for (int k = 0; k < MSEG / 256; k++) {
        int f = seg * MSEG + k * 256 + t;
        float4 bb = g_bb[f];
        bool ov = (bb.x <= x_hi + CULL_EPS) && (bb.y >= x_lo - CULL_EPS) &&
                  (bb.z <= y_hi + CULL_EPS) && (bb.w >= y_lo - CULL_EPS);
        if (ov) {
            float4 fa = g_fa[f];
            float4 fb = g_fb[f];
            float dxc = ctx - fa.z, dyc = cty - fa.w;
            float w0c = fa.x * dxc + fa.y * dyc;
            float w1c = fb.x * dxc + fb.y * dyc;
            float b0m = w0c + fabsf(fa.x) * hx + fabsf(fa.y) * hy;
            float b1m = w1c + fabsf(fb.x) * hx + fabsf(fb.y) * hy;
            float sa  = fa.x + fb.x, sb = fa.y + fb.y;
            float b2m = 1.0f - (w0c + w1c) + fabsf(sa) * hx + fabsf(sb) * hy;
            if (b0m >= -CULL_EPS && b1m >= -CULL_EPS && b2m >= -CULL_EPS) {
                int slot = atomicAdd(&s_cnt, 1);
                sA[slot] = fa;
                sB[slot] = fb;
                sR[slot] = g_r2[f];
            }
        }
    }
    __syncthreads();
    const int cnt = s_cnt;

    // this thread's 4 pixels (one row, 4 adjacent columns)
    const int row = t >> 4;
    const int grp = t & 15;
    const int r   = r0t + row;
    const int c0  = c0t + grp * 4;
    const float py = (float)(S_RAS - 1 - 2 * r) / (float)S_RAS;
    float px[4];
    #pragma unroll
    for (int j = 0; j < 4; j++)
        px[j] = (2.0f * (c0 + j) + 1.0f - S_RAS) / (float)S_RAS;

    float m[4] = {0.0f, 0.0f, 0.0f, 0.0f};   // max inv_z (inside faces all have iz > 0)

    #pragma unroll 2
    for (int i = 0; i < cnt; i++) {
        float4 fa = sA[i];
        float4 fb = sB[i];
        float  r2 = sR[i];
        float dy = py - fa.w;
        float t0 = fa.y * dy;
        float t1 = fb.y * dy;
        #pragma unroll
        for (int j = 0; j < 4; j++) {
            float dx = px[j] - fa.z;
            float w0 = fmaf(fa.x, dx, t0);
            float w1 = fmaf(fb.x, dx, t1);
            float ws = w0 + w1;
            if (w0 >= 0.0f && w1 >= 0.0f && ws <= 1.0f) {
                float iz = fmaf(w0, fb.z, fmaf(w1, fb.w, r2));
                m[j] = fmaxf(m[j], iz);
            }
        }
    }

    if (r < H_OUT && c0 < W_OUT) {
        float4 val = make_float4(m[0], m[1], m[2], m[3]);
        *reinterpret_cast<float4*>(&g_pm[seg * NPIX + r * W_OUT + c0]) = val;
    }
}

// ---------------------------------------------------------------------------
// 3) merge segments, write depth + sil
// ---------------------------------------------------------------------------
__global__ void finalize_kernel(float* __restrict__ out)
{
    int px = blockIdx.x * blockDim.x + threadIdx.x;
    if (px >= NPIX) return;
    float mv = g_pm[px];
    #pragma unroll
    for (int s = 1; s < NSEG; s++)
        mv = fmaxf(mv, g_pm[s * NPIX + px]);
    bool hit = mv > 0.0f;
    out[px]        = hit ? fminf(FAR_V, 1.0f / mv) : FAR_V;
    out[NPIX + px] = hit ? 1.0f : 0.0f;
}

// ---------------------------------------------------------------------------
extern "C" void kernel_launch(void* const* d_in, const int* in_sizes, int n_in,
                              void* d_out, int out_size)
{
    const float* verts = (const float*)d_in[0];   // [1,8192,3] f32
    const int*   faces = (const int*)  d_in[1];   // [1,2048,3] i32
    const float* Km    = (const float*)d_in[2];   // [1,3,3]
    const float* Rm    = (const float*)d_in[3];   // [1,3,3]
    const float* tm    = (const float*)d_in[4];   // [1,3,1]
    float* out = (float*)d_out;

    prep_kernel<<<M_F / 256, 256>>>(verts, faces, Km, Rm, tm);

    dim3 rgrid(TILES_X, TILES_Y, NSEG);           // 5 x 15 x 4 = 300 blocks
    raster_kernel<<<rgrid, 256>>>();

    finalize_kernel<<<(NPIX + 255) / 256, 256>>>(out);
}

// round 9
// speedup vs baseline: 2.2977x; 1.1047x over previous
#include <cuda_runtime.h>
#include <cuda_bf16.h>

#define H_OUT 228
#define W_OUT 304
#define S_RAS 304
#define N_V   8192
#define M_F   2048
#define TILE_W 32
#define TILE_H 8
#define TILES_X 10                // ceil(304/32)
#define TILES_Y 29                // ceil(228/8)
#define NTHR   128                // 2 px per thread (row-adjacent)
#define FCH    512                // faces per smem chunk
#define NPIX  (H_OUT * W_OUT)
#define FAR_V 100.0f
#define EPS_V 1e-7f
#define CULL_EPS 1e-4f

// scratch (no allocations allowed)
__device__ float4 g_fa[M_F];              // (a0, b0, x2, y2)
__device__ float4 g_fb[M_F];              // (a1, b1, r0-r2, r1-r2)
__device__ float  g_r2[M_F];              // 1/z2
__device__ float4 g_bb[M_F];              // (xmin, xmax, ymin, ymax); NaN if degenerate

// ---------------------------------------------------------------------------
// 1) fused vertex transform + face setup (one thread per face)
// ---------------------------------------------------------------------------
__global__ void __launch_bounds__(64) prep_kernel(const float* __restrict__ verts,
                                                  const int*   __restrict__ faces,
                                                  const float* __restrict__ Km,
                                                  const float* __restrict__ Rm,
                                                  const float* __restrict__ tm)
{
    int f = blockIdx.x * blockDim.x + threadIdx.x;
    if (f >= M_F) return;

    // issue all gathers up front for MLP
    int i0 = faces[3 * f + 0];
    int i1 = faces[3 * f + 1];
    int i2 = faces[3 * f + 2];
    float vu[3], vv_[3], vd[3];
    {
        const int idxs[3] = {i0, i1, i2};
        #pragma unroll
        for (int v = 0; v < 3; v++) {
            vu[v]  = __ldg(&verts[3 * idxs[v] + 0]);
            vv_[v] = __ldg(&verts[3 * idxs[v] + 1]);
            vd[v]  = __ldg(&verts[3 * idxs[v] + 2]);
        }
    }

    float k0 = Km[0], k1 = Km[1], k2 = Km[2];
    float k3 = Km[3], k4 = Km[4], k5 = Km[5];
    float k6 = Km[6], k7 = Km[7], k8 = Km[8];

    // adjugate inverse of K
    float c00 = k4 * k8 - k5 * k7;
    float c01 = k5 * k6 - k3 * k8;
    float c02 = k3 * k7 - k4 * k6;
    float det = k0 * c00 + k1 * c01 + k2 * c02;
    float id  = 1.0f / det;
    float i00 = c00 * id, i01 = (k2 * k7 - k1 * k8) * id, i02 = (k1 * k5 - k2 * k4) * id;
    float i10 = c01 * id, i11 = (k0 * k8 - k2 * k6) * id, i12 = (k2 * k3 - k0 * k5) * id;
    float i20 = c02 * id, i21 = (k1 * k6 - k0 * k7) * id, i22 = (k0 * k4 - k1 * k3) * id;

    float R0 = Rm[0], R1 = Rm[1], R2 = Rm[2];
    float R3 = Rm[3], R4 = Rm[4], R5 = Rm[5];
    float R6 = Rm[6], R7 = Rm[7], R8 = Rm[8];
    float t0_ = tm[0], t1_ = tm[1], t2_ = tm[2];

    float X[3], Y[3], Z[3];
    #pragma unroll
    for (int v = 0; v < 3; v++) {
        float p0 = vu[v]  * (float)W_OUT;
        float p1 = vv_[v] * (float)H_OUT;
        float d  = vd[v];

        float cx = (i00 * p0 + i01 * p1 + i02) * d;
        float cy = (i10 * p0 + i11 * p1 + i12) * d;
        float cz = (i20 * p0 + i21 * p1 + i22) * d;

        float qx = R0 * cx + R1 * cy + R2 * cz + t0_;
        float qy = R3 * cx + R4 * cy + R5 * cz + t1_;
        float qz = R6 * cx + R7 * cy + R8 * cz + t2_;

        float zd  = qz + EPS_V;
        float ppx = qx / zd;
        float ppy = qy / zd;

        float s0 = k0 * ppx + k1 * ppy + k2;
        float s1 = k3 * ppx + k4 * ppy + k5;

        float u2 = fminf(fmaxf(s0 / (float)W_OUT, 0.0f), 1.0f);
        float v2 = fminf(fmaxf(s1 / (float)H_OUT, 0.0f), 1.0f);

        X[v] = (u2 * (float)W_OUT) / (float)S_RAS * 2.0f - 1.0f;
        Y[v] = (v2 * (float)H_OUT) / (float)S_RAS * 2.0f - 1.0f;
        Z[v] = qz;
    }

    float y12 = Y[1] - Y[2];
    float x21 = X[2] - X[1];
    float y20 = Y[2] - Y[0];
    float x02 = X[0] - X[2];

    float denom = y12 * (X[0] - X[2]) + x21 * (Y[0] - Y[2]);
    bool  ok    = fabsf(denom) > 1e-10f;
    float inv   = 1.0f / (ok ? denom : 1.0f);

    float a0 = y12 * inv, b0 = x21 * inv;
    float a1 = y20 * inv, b1 = x02 * inv;
    float r0 = 1.0f / Z[0], r1 = 1.0f / Z[1], r2 = 1.0f / Z[2];

    g_fa[f] = make_float4(a0, b0, X[2], Y[2]);
    g_fb[f] = make_float4(a1, b1, r0 - r2, r1 - r2);
    g_r2[f] = r2;

    float xmn = fminf(X[0], fminf(X[1], X[2]));
    float xmx = fmaxf(X[0], fmaxf(X[1], X[2]));
    float ymn = fminf(Y[0], fminf(Y[1], Y[2]));
    float ymx = fmaxf(Y[0], fmaxf(Y[1], Y[2]));
    float nanv = __int_as_float(0x7fc00000);
    g_bb[f] = ok ? make_float4(xmn, xmx, ymn, ymx)
                 : make_float4(nanv, nanv, nanv, nanv);
}

// ---------------------------------------------------------------------------
// 2) tiled raster: 32x8-px tile per block, 128 threads, 2 px/thread.
//    All 2048 faces stream through smem in 4 chunks of 512 with
//    bbox + conservative-edge culling; final depth/sil written directly.
// ---------------------------------------------------------------------------
__global__ void __launch_bounds__(NTHR) raster_kernel(float* __restrict__ out)
{
    __shared__ float4 sA[FCH];
    __shared__ float4 sB[FCH];
    __shared__ float  sR[FCH];
    __shared__ int    s_cnt;

    const int tX = blockIdx.x, tY = blockIdx.y;
    const int t  = threadIdx.x;

    // tile pixel-center bounds in ndc (py decreases with row index)
    const int c0t = tX * TILE_W, r0t = tY * TILE_H;
    const float x_lo = (2.0f * c0t + 1.0f - S_RAS) / (float)S_RAS;
    const float x_hi = (2.0f * (c0t + TILE_W - 1) + 1.0f - S_RAS) / (float)S_RAS;
    const float y_hi = (float)(S_RAS - 1 - 2 * r0t) / (float)S_RAS;
    const float y_lo = (float)(S_RAS - 1 - 2 * (r0t + TILE_H - 1)) / (float)S_RAS;
    const float ctx = 0.5f * (x_lo + x_hi), cty = 0.5f * (y_lo + y_hi);
    const float hx  = 0.5f * (x_hi - x_lo), hy  = 0.5f * (y_hi - y_lo);

    // this thread's 2 adjacent pixels (same row)
    const int r  = r0t + (t >> 4);
    const int c0 = c0t + 2 * (t & 15);
    const float py  = (float)(S_RAS - 1 - 2 * r) / (float)S_RAS;
    const float px0 = (2.0f * c0 + 1.0f - S_RAS) / (float)S_RAS;
    const float px1 = (2.0f * c0 + 3.0f - S_RAS) / (float)S_RAS;

    float m0 = 0.0f, m1 = 0.0f;    // max inv_z (all inside faces have iz > 0)

    for (int base = 0; base < M_F; base += FCH) {
        __syncthreads();           // previous chunk fully consumed
        if (t == 0) s_cnt = 0;
        __syncthreads();

        // cull + compact: 512 faces, 4 per thread
        #pragma unroll
        for (int k = 0; k < FCH / NTHR; k++) {
            int f = base + k * NTHR + t;
            float4 bb = g_bb[f];
            bool ov = (bb.x <= x_hi + CULL_EPS) && (bb.y >= x_lo - CULL_EPS) &&
                      (bb.z <= y_hi + CULL_EPS) && (bb.w >= y_lo - CULL_EPS);
            if (ov) {
                float4 fa = g_fa[f];
                float4 fb = g_fb[f];
                float dxc = ctx - fa.z, dyc = cty - fa.w;
                float w0c = fa.x * dxc + fa.y * dyc;
                float w1c = fb.x * dxc + fb.y * dyc;
                float b0m = w0c + fabsf(fa.x) * hx + fabsf(fa.y) * hy;
                float b1m = w1c + fabsf(fb.x) * hx + fabsf(fb.y) * hy;
                float sa  = fa.x + fb.x, sb = fa.y + fb.y;
                float b2m = 1.0f - (w0c + w1c) + fabsf(sa) * hx + fabsf(sb) * hy;
                if (b0m >= -CULL_EPS && b1m >= -CULL_EPS && b2m >= -CULL_EPS) {
                    int slot = atomicAdd(&s_cnt, 1);
                    sA[slot] = fa;
                    sB[slot] = fb;
                    sR[slot] = g_r2[f];
                }
            }
        }
        __syncthreads();
        const int cnt = s_cnt;

        #pragma unroll 2
        for (int i = 0; i < cnt; i++) {
            float4 fa = sA[i];
            float4 fb = sB[i];
            float  r2 = sR[i];
            float dy = py - fa.w;
            float t0 = fa.y * dy;
            float t1 = fb.y * dy;

            float dx0 = px0 - fa.z;
            float w0a = fmaf(fa.x, dx0, t0);
            float w1a = fmaf(fb.x, dx0, t1);
            float wsa = w0a + w1a;
            if (w0a >= 0.0f && w1a >= 0.0f && wsa <= 1.0f) {
                float iz = fmaf(w0a, fb.z, fmaf(w1a, fb.w, r2));
                m0 = fmaxf(m0, iz);
            }

            float dx1 = px1 - fa.z;
            float w0b = fmaf(fa.x, dx1, t0);
            float w1b = fmaf(fb.x, dx1, t1);
            float wsb = w0b + w1b;
            if (w0b >= 0.0f && w1b >= 0.0f && wsb <= 1.0f) {
                float iz = fmaf(w0b, fb.z, fmaf(w1b, fb.w, r2));
                m1 = fmaxf(m1, iz);
            }
        }
    }

    if (r < H_OUT && c0 < W_OUT) {
        float d0 = (m0 > 0.0f) ? fminf(FAR_V, 1.0f / m0) : FAR_V;
        float d1 = (m1 > 0.0f) ? fminf(FAR_V, 1.0f / m1) : FAR_V;
        float s0 = (m0 > 0.0f) ? 1.0f : 0.0f;
        float s1 = (m1 > 0.0f) ? 1.0f : 0.0f;
        *reinterpret_cast<float2*>(&out[r * W_OUT + c0])        = make_float2(d0, d1);
        *reinterpret_cast<float2*>(&out[NPIX + r * W_OUT + c0]) = make_float2(s0, s1);
    }
}

// ---------------------------------------------------------------------------
extern "C" void kernel_launch(void* const* d_in, const int* in_sizes, int n_in,
                              void* d_out, int out_size)
{
    const float* verts = (const float*)d_in[0];   // [1,8192,3] f32
    const int*   faces = (const int*)  d_in[1];   // [1,2048,3] i32
    const float* Km    = (const float*)d_in[2];   // [1,3,3]
    const float* Rm    = (const float*)d_in[3];   // [1,3,3]
    const float* tm    = (const float*)d_in[4];   // [1,3,1]
    float* out = (float*)d_out;

    prep_kernel<<<M_F / 64, 64>>>(verts, faces, Km, Rm, tm);

    dim3 rgrid(TILES_X, TILES_Y);                 // 10 x 29 = 290 blocks
    raster_kernel<<<rgrid, NTHR>>>(out);
}

// round 10
// speedup vs baseline: 2.7245x; 1.1857x over previous
#include <cuda_runtime.h>
#include <cuda_bf16.h>

#define H_OUT 228
#define W_OUT 304
#define S_RAS 304
#define N_V   8192
#define M_F   2048
#define TILE_W 32
#define TILE_H 8
#define TILES_X 10                // ceil(304/32)
#define TILES_Y 29                // ceil(228/8)
#define NTHR   256                // 1 px per thread
#define FCH    512                // faces per smem chunk
#define NPIX  (H_OUT * W_OUT)
#define FAR_V 100.0f
#define EPS_V 1e-7f
#define CULL_EPS 1e-4f

// scratch (no allocations allowed)
__device__ float4 g_fa[M_F];              // (a0, b0, x2, y2)
__device__ float4 g_fb[M_F];              // (a1, b1, r0-r2, r1-r2)
__device__ float  g_r2[M_F];              // 1/z2
__device__ float4 g_bb[M_F];              // (xmin, xmax, ymin, ymax); NaN if degenerate

// ---------------------------------------------------------------------------
// 1) fused vertex transform + face setup (one thread per face)
// ---------------------------------------------------------------------------
__global__ void __launch_bounds__(64) prep_kernel(const float* __restrict__ verts,
                                                  const int*   __restrict__ faces,
                                                  const float* __restrict__ Km,
                                                  const float* __restrict__ Rm,
                                                  const float* __restrict__ tm)
{
    int f = blockIdx.x * blockDim.x + threadIdx.x;
    if (f >= M_F) return;

    // issue all gathers up front for MLP
    int i0 = faces[3 * f + 0];
    int i1 = faces[3 * f + 1];
    int i2 = faces[3 * f + 2];
    float vu[3], vv_[3], vd[3];
    {
        const int idxs[3] = {i0, i1, i2};
        #pragma unroll
        for (int v = 0; v < 3; v++) {
            vu[v]  = __ldg(&verts[3 * idxs[v] + 0]);
            vv_[v] = __ldg(&verts[3 * idxs[v] + 1]);
            vd[v]  = __ldg(&verts[3 * idxs[v] + 2]);
        }
    }

    float k0 = Km[0], k1 = Km[1], k2 = Km[2];
    float k3 = Km[3], k4 = Km[4], k5 = Km[5];
    float k6 = Km[6], k7 = Km[7], k8 = Km[8];

    // adjugate inverse of K
    float c00 = k4 * k8 - k5 * k7;
    float c01 = k5 * k6 - k3 * k8;
    float c02 = k3 * k7 - k4 * k6;
    float det = k0 * c00 + k1 * c01 + k2 * c02;
    float id  = 1.0f / det;
    float i00 = c00 * id, i01 = (k2 * k7 - k1 * k8) * id, i02 = (k1 * k5 - k2 * k4) * id;
    float i10 = c01 * id, i11 = (k0 * k8 - k2 * k6) * id, i12 = (k2 * k3 - k0 * k5) * id;
    float i20 = c02 * id, i21 = (k1 * k6 - k0 * k7) * id, i22 = (k0 * k4 - k1 * k3) * id;

    float R0 = Rm[0], R1 = Rm[1], R2 = Rm[2];
    float R3 = Rm[3], R4 = Rm[4], R5 = Rm[5];
    float R6 = Rm[6], R7 = Rm[7], R8 = Rm[8];
    float t0_ = tm[0], t1_ = tm[1], t2_ = tm[2];

    float X[3], Y[3], Z[3];
    #pragma unroll
    for (int v = 0; v < 3; v++) {
        float p0 = vu[v]  * (float)W_OUT;
        float p1 = vv_[v] * (float)H_OUT;
        float d  = vd[v];

        float cx = (i00 * p0 + i01 * p1 + i02) * d;
        float cy = (i10 * p0 + i11 * p1 + i12) * d;
        float cz = (i20 * p0 + i21 * p1 + i22) * d;

        float qx = R0 * cx + R1 * cy + R2 * cz + t0_;
        float qy = R3 * cx + R4 * cy + R5 * cz + t1_;
        float qz = R6 * cx + R7 * cy + R8 * cz + t2_;

        float zd  = qz + EPS_V;
        float ppx = qx / zd;
        float ppy = qy / zd;

        float s0 = k0 * ppx + k1 * ppy + k2;
        float s1 = k3 * ppx + k4 * ppy + k5;

        float u2 = fminf(fmaxf(s0 / (float)W_OUT, 0.0f), 1.0f);
        float v2 = fminf(fmaxf(s1 / (float)H_OUT, 0.0f), 1.0f);

        X[v] = (u2 * (float)W_OUT) / (float)S_RAS * 2.0f - 1.0f;
        Y[v] = (v2 * (float)H_OUT) / (float)S_RAS * 2.0f - 1.0f;
        Z[v] = qz;
    }

    float y12 = Y[1] - Y[2];
    float x21 = X[2] - X[1];
    float y20 = Y[2] - Y[0];
    float x02 = X[0] - X[2];

    float denom = y12 * (X[0] - X[2]) + x21 * (Y[0] - Y[2]);
    bool  ok    = fabsf(denom) > 1e-10f;
    float inv   = 1.0f / (ok ? denom : 1.0f);

    float a0 = y12 * inv, b0 = x21 * inv;
    float a1 = y20 * inv, b1 = x02 * inv;
    float r0 = 1.0f / Z[0], r1 = 1.0f / Z[1], r2 = 1.0f / Z[2];

    g_fa[f] = make_float4(a0, b0, X[2], Y[2]);
    g_fb[f] = make_float4(a1, b1, r0 - r2, r1 - r2);
    g_r2[f] = r2;

    float xmn = fminf(X[0], fminf(X[1], X[2]));
    float xmx = fmaxf(X[0], fmaxf(X[1], X[2]));
    float ymn = fminf(Y[0], fminf(Y[1], Y[2]));
    float ymx = fmaxf(Y[0], fmaxf(Y[1], Y[2]));
    float nanv = __int_as_float(0x7fc00000);
    g_bb[f] = ok ? make_float4(xmn, xmx, ymn, ymx)
                 : make_float4(nanv, nanv, nanv, nanv);
}

// ---------------------------------------------------------------------------
// 2) tiled raster: 32x8-px tile per block, 256 threads, 1 px/thread.
//    Faces stream through smem in chunks of 512 with bbox + conservative
//    edge culling; branchless predicated inner loop.
// ---------------------------------------------------------------------------
__global__ void __launch_bounds__(NTHR) raster_kernel(float* __restrict__ out)
{
    __shared__ float4 sA[FCH];
    __shared__ float4 sB[FCH];
    __shared__ float  sR[FCH];
    __shared__ int    s_cnt;

    const int tX = blockIdx.x, tY = blockIdx.y;
    const int t  = threadIdx.x;

    // tile pixel-center bounds in ndc (py decreases with row index)
    const int c0t = tX * TILE_W, r0t = tY * TILE_H;
    const float x_lo = (2.0f * c0t + 1.0f - S_RAS) / (float)S_RAS;
    const float x_hi = (2.0f * (c0t + TILE_W - 1) + 1.0f - S_RAS) / (float)S_RAS;
    const float y_hi = (float)(S_RAS - 1 - 2 * r0t) / (float)S_RAS;
    const float y_lo = (float)(S_RAS - 1 - 2 * (r0t + TILE_H - 1)) / (float)S_RAS;
    const float ctx = 0.5f * (x_lo + x_hi), cty = 0.5f * (y_lo + y_hi);
    const float hx  = 0.5f * (x_hi - x_lo), hy  = 0.5f * (y_hi - y_lo);

    // this thread's pixel
    const int r = r0t + (t >> 5);
    const int c = c0t + (t & 31);
    const float py = (float)(S_RAS - 1 - 2 * r) / (float)S_RAS;
    const float px = (2.0f * c + 1.0f - S_RAS) / (float)S_RAS;

    float m = 0.0f;                // max inv_z (all inside faces have iz > 0)

    for (int base = 0; base < M_F; base += FCH) {
        __syncthreads();           // previous chunk fully consumed
        if (t == 0) s_cnt = 0;
        __syncthreads();

        // cull + compact: 512 faces, 2 per thread
        #pragma unroll
        for (int k = 0; k < FCH / NTHR; k++) {
            int f = base + k * NTHR + t;
            float4 bb = g_bb[f];
            bool ov = (bb.x <= x_hi + CULL_EPS) && (bb.y >= x_lo - CULL_EPS) &&
                      (bb.z <= y_hi + CULL_EPS) && (bb.w >= y_lo - CULL_EPS);
            if (ov) {
                float4 fa = g_fa[f];
                float4 fb = g_fb[f];
                float dxc = ctx - fa.z, dyc = cty - fa.w;
                float w0c = fa.x * dxc + fa.y * dyc;
                float w1c = fb.x * dxc + fb.y * dyc;
                float b0m = w0c + fabsf(fa.x) * hx + fabsf(fa.y) * hy;
                float b1m = w1c + fabsf(fb.x) * hx + fabsf(fb.y) * hy;
                float sa  = fa.x + fb.x, sb = fa.y + fb.y;
                float b2m = 1.0f - (w0c + w1c) + fabsf(sa) * hx + fabsf(sb) * hy;
                if (b0m >= -CULL_EPS && b1m >= -CULL_EPS && b2m >= -CULL_EPS) {
                    int slot = atomicAdd(&s_cnt, 1);
                    sA[slot] = fa;
                    sB[slot] = fb;
                    sR[slot] = g_r2[f];
                }
            }
        }
        __syncthreads();
        const int cnt = s_cnt;

        #pragma unroll 4
        for (int i = 0; i < cnt; i++) {
            float4 fa = sA[i];
            float4 fb = sB[i];
            float  r2 = sR[i];
            float dy = py - fa.w;
            float t0 = fa.y * dy;
            float t1 = fb.y * dy;
            float dx = px - fa.z;
            float w0 = fmaf(fa.x, dx, t0);
            float w1 = fmaf(fb.x, dx, t1);
            float ws = w0 + w1;
            float iz = fmaf(w0, fb.z, fmaf(w1, fb.w, r2));
            float mn = fminf(fminf(w0, w1), 1.0f - ws);
            m = fmaxf(m, (mn >= 0.0f) ? iz : 0.0f);   // branchless
        }
    }

    if (r < H_OUT && c < W_OUT) {
        bool hit = m > 0.0f;
        out[r * W_OUT + c]        = hit ? fminf(FAR_V, 1.0f / m) : FAR_V;
        out[NPIX + r * W_OUT + c] = hit ? 1.0f : 0.0f;
    }
}

// ---------------------------------------------------------------------------
extern "C" void kernel_launch(void* const* d_in, const int* in_sizes, int n_in,
                              void* d_out, int out_size)
{
    const float* verts = (const float*)d_in[0];   // [1,8192,3] f32
    const int*   faces = (const int*)  d_in[1];   // [1,2048,3] i32
    const float* Km    = (const float*)d_in[2];   // [1,3,3]
    const float* Rm    = (const float*)d_in[3];   // [1,3,3]
    const float* tm    = (const float*)d_in[4];   // [1,3,1]
    float* out = (float*)d_out;

    prep_kernel<<<M_F / 64, 64>>>(verts, faces, Km, Rm, tm);

    dim3 rgrid(TILES_X, TILES_Y);                 // 10 x 29 = 290 blocks
    raster_kernel<<<rgrid, NTHR>>>(out);
}

// round 11
// speedup vs baseline: 3.3208x; 1.2189x over previous
#include <cuda_runtime.h>
#include <cuda_bf16.h>

#define H_OUT 228
#define W_OUT 304
#define S_RAS 304
#define N_V   8192
#define M_F   2048
#define NSEG  2
#define MSEG  (M_F / NSEG)        // 1024, exactly one smem chunk
#define TILE_W 32
#define TILE_H 8
#define TILES_X 10                // ceil(304/32)
#define TILES_Y 29                // ceil(228/8)
#define NTHR   256                // 1 px per thread
#define NPIX  (H_OUT * W_OUT)     // 69312 (divisible by 4)
#define FAR_V 100.0f
#define EPS_V 1e-7f
#define CULL_EPS 1e-4f

// scratch (no allocations allowed)
__device__ float4 g_fa[M_F];              // (a0, b0, x2, y2)
__device__ float4 g_fb[M_F];              // (a1, b1, r0-r2, r1-r2)
__device__ float  g_r2[M_F];              // 1/z2
__device__ float4 g_bb[M_F];              // (xmin, xmax, ymin, ymax); NaN if degenerate
__device__ float  g_pm[NSEG * NPIX];      // per-segment max inv_z (every slot written)

// ---------------------------------------------------------------------------
// 1) fused vertex transform + face setup (one thread per face)
// ---------------------------------------------------------------------------
__global__ void __launch_bounds__(64) prep_kernel(const float* __restrict__ verts,
                                                  const int*   __restrict__ faces,
                                                  const float* __restrict__ Km,
                                                  const float* __restrict__ Rm,
                                                  const float* __restrict__ tm)
{
    int f = blockIdx.x * blockDim.x + threadIdx.x;
    if (f >= M_F) return;

    // issue all gathers up front for MLP
    int i0 = faces[3 * f + 0];
    int i1 = faces[3 * f + 1];
    int i2 = faces[3 * f + 2];
    float vu[3], vv_[3], vd[3];
    {
        const int idxs[3] = {i0, i1, i2};
        #pragma unroll
        for (int v = 0; v < 3; v++) {
            vu[v]  = __ldg(&verts[3 * idxs[v] + 0]);
            vv_[v] = __ldg(&verts[3 * idxs[v] + 1]);
            vd[v]  = __ldg(&verts[3 * idxs[v] + 2]);
        }
    }

    float k0 = Km[0], k1 = Km[1], k2 = Km[2];
    float k3 = Km[3], k4 = Km[4], k5 = Km[5];
    float k6 = Km[6], k7 = Km[7], k8 = Km[8];

    // adjugate inverse of K
    float c00 = k4 * k8 - k5 * k7;
    float c01 = k5 * k6 - k3 * k8;
    float c02 = k3 * k7 - k4 * k6;
    float det = k0 * c00 + k1 * c01 + k2 * c02;
    float id  = 1.0f / det;
    float i00 = c00 * id, i01 = (k2 * k7 - k1 * k8) * id, i02 = (k1 * k5 - k2 * k4) * id;
    float i10 = c01 * id, i11 = (k0 * k8 - k2 * k6) * id, i12 = (k2 * k3 - k0 * k5) * id;
    float i20 = c02 * id, i21 = (k1 * k6 - k0 * k7) * id, i22 = (k0 * k4 - k1 * k3) * id;

    float R0 = Rm[0], R1 = Rm[1], R2 = Rm[2];
    float R3 = Rm[3], R4 = Rm[4], R5 = Rm[5];
    float R6 = Rm[6], R7 = Rm[7], R8 = Rm[8];
    float t0_ = tm[0], t1_ = tm[1], t2_ = tm[2];

    float X[3], Y[3], Z[3];
    #pragma unroll
    for (int v = 0; v < 3; v++) {
        float p0 = vu[v]  * (float)W_OUT;
        float p1 = vv_[v] * (float)H_OUT;
        float d  = vd[v];

        float cx = (i00 * p0 + i01 * p1 + i02) * d;
        float cy = (i10 * p0 + i11 * p1 + i12) * d;
        float cz = (i20 * p0 + i21 * p1 + i22) * d;

        float qx = R0 * cx + R1 * cy + R2 * cz + t0_;
        float qy = R3 * cx + R4 * cy + R5 * cz + t1_;
        float qz = R6 * cx + R7 * cy + R8 * cz + t2_;

        float zd  = qz + EPS_V;
        float ppx = qx / zd;
        float ppy = qy / zd;

        float s0 = k0 * ppx + k1 * ppy + k2;
        float s1 = k3 * ppx + k4 * ppy + k5;

        float u2 = fminf(fmaxf(s0 / (float)W_OUT, 0.0f), 1.0f);
        float v2 = fminf(fmaxf(s1 / (float)H_OUT, 0.0f), 1.0f);

        X[v] = (u2 * (float)W_OUT) / (float)S_RAS * 2.0f - 1.0f;
        Y[v] = (v2 * (float)H_OUT) / (float)S_RAS * 2.0f - 1.0f;
        Z[v] = qz;
    }

    float y12 = Y[1] - Y[2];
    float x21 = X[2] - X[1];
    float y20 = Y[2] - Y[0];
    float x02 = X[0] - X[2];

    float denom = y12 * (X[0] - X[2]) + x21 * (Y[0] - Y[2]);
    bool  ok    = fabsf(denom) > 1e-10f;
    float inv   = 1.0f / (ok ? denom : 1.0f);

    float a0 = y12 * inv, b0 = x21 * inv;
    float a1 = y20 * inv, b1 = x02 * inv;
    float r0 = 1.0f / Z[0], r1 = 1.0f / Z[1], r2 = 1.0f / Z[2];

    g_fa[f] = make_float4(a0, b0, X[2], Y[2]);
    g_fb[f] = make_float4(a1, b1, r0 - r2, r1 - r2);
    g_r2[f] = r2;

    float xmn = fminf(X[0], fminf(X[1], X[2]));
    float xmx = fmaxf(X[0], fmaxf(X[1], X[2]));
    float ymn = fminf(Y[0], fminf(Y[1], Y[2]));
    float ymx = fmaxf(Y[0], fmaxf(Y[1], Y[2]));
    float nanv = __int_as_float(0x7fc00000);
    g_bb[f] = ok ? make_float4(xmn, xmx, ymn, ymx)
                 : make_float4(nanv, nanv, nanv, nanv);
}

// ---------------------------------------------------------------------------
// 2) tiled raster: block = (tileX, tileY, face-segment). 32x8-px tile,
//    256 threads (1 px/thread), 1024 faces/segment in ONE smem pass.
//    Cull (bbox + conservative edge bounds) -> compact -> branchless sweep.
//    Per-segment max inv_z written to unique g_pm slots (no atomics).
// ---------------------------------------------------------------------------
__global__ void __launch_bounds__(NTHR) raster_kernel()
{
    __shared__ float4 sA[MSEG];
    __shared__ float4 sB[MSEG];
    __shared__ float  sR[MSEG];
    __shared__ int    s_cnt;

    const int tX = blockIdx.x, tY = blockIdx.y, seg = blockIdx.z;
    const int t  = threadIdx.x;
    if (t == 0) s_cnt = 0;
    __syncthreads();

    // tile pixel-center bounds in ndc (py decreases with row index)
    const int c0t = tX * TILE_W, r0t = tY * TILE_H;
    const float x_lo = (2.0f * c0t + 1.0f - S_RAS) / (float)S_RAS;
    const float x_hi = (2.0f * (c0t + TILE_W - 1) + 1.0f - S_RAS) / (float)S_RAS;
    const float y_hi = (float)(S_RAS - 1 - 2 * r0t) / (float)S_RAS;
    const float y_lo = (float)(S_RAS - 1 - 2 * (r0t + TILE_H - 1)) / (float)S_RAS;
    const float ctx = 0.5f * (x_lo + x_hi), cty = 0.5f * (y_lo + y_hi);
    const float hx  = 0.5f * (x_hi - x_lo), hy  = 0.5f * (y_hi - y_lo);

    // cull + compact: 1024 faces, 4 per thread
    #pragma unroll
    for (int k = 0; k < MSEG / NTHR; k++) {
        int f = seg * MSEG + k * NTHR + t;
        float4 bb = g_bb[f];
        bool ov = (bb.x <= x_hi + CULL_EPS) && (bb.y >= x_lo - CULL_EPS) &&
                  (bb.z <= y_hi + CULL_EPS) && (bb.w >= y_lo - CULL_EPS);
        if (ov) {
            float4 fa = g_fa[f];
            float4 fb = g_fb[f];
            float dxc = ctx - fa.z, dyc = cty - fa.w;
            float w0c = fa.x * dxc + fa.y * dyc;
            float w1c = fb.x * dxc + fb.y * dyc;
            float b0m = w0c + fabsf(fa.x) * hx + fabsf(fa.y) * hy;
            float b1m = w1c + fabsf(fb.x) * hx + fabsf(fb.y) * hy;
            float sa  = fa.x + fb.x, sb = fa.y + fb.y;
            float b2m = 1.0f - (w0c + w1c) + fabsf(sa) * hx + fabsf(sb) * hy;
            if (b0m >= -CULL_EPS && b1m >= -CULL_EPS && b2m >= -CULL_EPS) {
                int slot = atomicAdd(&s_cnt, 1);
                sA[slot] = fa;
                sB[slot] = fb;
                sR[slot] = g_r2[f];
            }
        }
    }
    __syncthreads();
    const int cnt = s_cnt;

    // this thread's pixel
    const int r = r0t + (t >> 5);
    const int c = c0t + (t & 31);
    const float py = (float)(S_RAS - 1 - 2 * r) / (float)S_RAS;
    const float px = (2.0f * c + 1.0f - S_RAS) / (float)S_RAS;

    float m = 0.0f;                // max inv_z (all inside faces have iz > 0)

    #pragma unroll 4
    for (int i = 0; i < cnt; i++) {
        float4 fa = sA[i];
        float4 fb = sB[i];
        float  r2 = sR[i];
        float dy = py - fa.w;
        float t0 = fa.y * dy;
        float t1 = fb.y * dy;
        float dx = px - fa.z;
        float w0 = fmaf(fa.x, dx, t0);
        float w1 = fmaf(fb.x, dx, t1);
        float ws = w0 + w1;
        float iz = fmaf(w0, fb.z, fmaf(w1, fb.w, r2));
        float mn = fminf(fminf(w0, w1), 1.0f - ws);
        m = fmaxf(m, (mn >= 0.0f) ? iz : 0.0f);   // branchless
    }

    if (r < H_OUT && c < W_OUT)
        g_pm[seg * NPIX + r * W_OUT + c] = m;
}

// ---------------------------------------------------------------------------
// 3) merge segments, write depth + sil (vectorized)
// ---------------------------------------------------------------------------
__global__ void finalize_kernel(float* __restrict__ out)
{
    int q = blockIdx.x * blockDim.x + threadIdx.x;    // quad index
    if (q >= NPIX / 4) return;
    float4 a = *reinterpret_cast<const float4*>(&g_pm[4 * q]);
    float4 b = *reinterpret_cast<const float4*>(&g_pm[NPIX + 4 * q]);
    float mv[4] = { fmaxf(a.x, b.x), fmaxf(a.y, b.y),
                    fmaxf(a.z, b.z), fmaxf(a.w, b.w) };
    float4 dep, sil;
    float* dp = &dep.x; float* sp = &sil.x;
    #pragma unroll
    for (int j = 0; j < 4; j++) {
        bool hit = mv[j] > 0.0f;
        dp[j] = hit ? fminf(FAR_V, 1.0f / mv[j]) : FAR_V;
        sp[j] = hit ? 1.0f : 0.0f;
    }
    *reinterpret_cast<float4*>(&out[4 * q])        = dep;
    *reinterpret_cast<float4*>(&out[NPIX + 4 * q]) = sil;
}

// ---------------------------------------------------------------------------
extern "C" void kernel_launch(void* const* d_in, const int* in_sizes, int n_in,
                              void* d_out, int out_size)
{
    const float* verts = (const float*)d_in[0];   // [1,8192,3] f32
    const int*   faces = (const int*)  d_in[1];   // [1,2048,3] i32
    const float* Km    = (const float*)d_in[2];   // [1,3,3]
    const float* Rm    = (const float*)d_in[3];   // [1,3,3]
    const float* tm    = (const float*)d_in[4];   // [1,3,1]
    float* out = (float*)d_out;

    prep_kernel<<<M_F / 64, 64>>>(verts, faces, Km, Rm, tm);

    dim3 rgrid(TILES_X, TILES_Y, NSEG);           // 10 x 29 x 2 = 580 blocks
    raster_kernel<<<rgrid, NTHR>>>();

    finalize_kernel<<<(NPIX / 4 + 127) / 128, 128>>>(out);
}